// round 6
// baseline (speedup 1.0000x reference)
#include <cuda_runtime.h>
#include <math.h>

#define H 32
#define F 8
#define TCH 32
#define NWARP 8
#define SEG (TCH / NWARP)   // 4
#define NTHR (NWARP * 32)   // 256
#define FULL 0xffffffffu

typedef unsigned long long ull;

// Folded weights computed once per launch by setup_kernel.
__device__ float g_wX[4 * F * H];   // m=0 W_embed, m=1 We@Wd1, m=2 We@Wg1, m=3 We@Wd2
__device__ float g_bias[4 * H];
__device__ float g_A[2 * H];        // exp(A_log)

struct SmemLayout {
    float4 xs[2][TCH * F / 4];      // double-buffered x chunks (2KB)
    float4 cAXGE[2][TCH * H];       // {a1, xi1, g1, e}  (32KB)
    float  cU2[2][TCH * H];         // u2 (8KB)
    float  cV[TCH * H];             // v rows (4KB, 16B-aligned rows)
    float2 segAX[2][NWARP * H];     // block-1 segment transforms
    float2 seg2[2][NWARP * H];      // block-2 segment transforms
    float  hlast[H];
    float2 swp01[F * H];            // paired {W0,W1}[j][lane]
    float2 swp23[F * H];            // paired {W2,W3}[j][lane]
    float2 swd2p[(H / 2) * H];      // paired Wd2 rows {2p,2p+1}[lane]
    float  sbias[4 * H];
    float  sA[2 * H];
    float  sWg2[H * H];
    float  sW1[H * H];
    float  sbg2[H];
    float  sb1[H];
    float  sW2[H];
    float  sgam[H];
    float  sbet[H];
    float  sb2;
};

__device__ __forceinline__ float ex2f(float x) { float r; asm("ex2.approx.f32 %0,%1;" : "=f"(r) : "f"(x)); return r; }
__device__ __forceinline__ float lg2f(float x) { float r; asm("lg2.approx.f32 %0,%1;" : "=f"(r) : "f"(x)); return r; }
__device__ __forceinline__ float tanh_f(float x) { float r; asm("tanh.approx.f32 %0,%1;" : "=f"(r) : "f"(x)); return r; }

__device__ __forceinline__ ull pack2(float lo, float hi) {
    ull r; asm("mov.b64 %0, {%1, %2};" : "=l"(r) : "r"(__float_as_uint(lo)), "r"(__float_as_uint(hi)));
    return r;
}
__device__ __forceinline__ ull splat2(float x) {
    ull r; asm("mov.b64 %0, {%1, %1};" : "=l"(r) : "r"(__float_as_uint(x)));
    return r;
}
__device__ __forceinline__ float2 unpack2(ull v) {
    unsigned lo, hi; asm("mov.b64 {%0, %1}, %2;" : "=r"(lo), "=r"(hi) : "l"(v));
    return make_float2(__uint_as_float(lo), __uint_as_float(hi));
}
__device__ __forceinline__ void fma2(ull& d, ull a, ull b) {
    asm("fma.rn.f32x2 %0, %1, %2, %0;" : "+l"(d) : "l"(a), "l"(b));
}

// d = softplus(u), a = exp(-A*d), computed in log2 domain: 3 MUFU total.
__device__ __forceinline__ void splus_decay(float u, float A, float& d, float& a) {
    const float L2E = 1.4426950408889634f;
    const float LN2 = 0.6931471805599453f;
    float p = ex2f(-fabsf(u) * L2E);
    float q = lg2f(1.f + p);
    float r = fmaf(fmaxf(u, 0.f), L2E, q);  // log2(1+e^u)
    d = r * LN2;
    a = ex2f(-A * r);
}

__device__ __forceinline__ float sigmoid_f(float u) {
    return fmaf(tanh_f(0.5f * u), 0.5f, 0.5f);
}

__device__ __forceinline__ float gelu_f(float u) {
    float inner = 0.7978845608028654f * fmaf(0.044715f * u, u * u, u);
    float ex = ex2f(2.f * inner * 1.4426950408889634f);
    float th = 1.f - __fdividef(2.f, ex + 1.f);
    return 0.5f * u * (1.f + th);
}

__device__ __forceinline__ float warp_allsum(float v) {
    #pragma unroll
    for (int off = 16; off; off >>= 1) v += __shfl_xor_sync(FULL, v, off);
    return v;
}

__global__ void setup_kernel(const float* __restrict__ We, const float* __restrict__ be,
                             const float* __restrict__ Wd, const float* __restrict__ bd,
                             const float* __restrict__ Alog, const float* __restrict__ Wg,
                             const float* __restrict__ bg) {
    int tid = threadIdx.x;
    for (int idx = tid; idx < F * H; idx += blockDim.x) g_wX[idx] = We[idx];
    for (int idx = tid; idx < 3 * F * H; idx += blockDim.x) {
        int m = idx / (F * H);
        int r = idx % (F * H);
        int f = r / H, k = r % H;
        const float* M = (m == 0) ? Wd : (m == 1) ? Wg : (Wd + H * H);
        float s = 0.f;
        for (int h = 0; h < H; h++) s += We[f * H + h] * M[h * H + k];
        g_wX[(m + 1) * F * H + r] = s;
    }
    for (int idx = tid; idx < 4 * H; idx += blockDim.x) {
        int m = idx / H, k = idx % H;
        float v;
        if (m == 0) v = be[k];
        else {
            const float* M; const float* bb;
            if (m == 1)      { M = Wd;         bb = bd;     }
            else if (m == 2) { M = Wg;         bb = bg;     }
            else             { M = Wd + H * H; bb = bd + H; }
            float s = 0.f;
            for (int h = 0; h < H; h++) s += be[h] * M[h * H + k];
            v = s + bb[k];
        }
        g_bias[idx] = v;
    }
    for (int idx = tid; idx < 2 * H; idx += blockDim.x) g_A[idx] = expf(Alog[idx]);
}

__global__ void __launch_bounds__(NTHR, 2)
forecast_kernel(const float* __restrict__ x,
                const float* __restrict__ Wd,
                const float* __restrict__ Wg, const float* __restrict__ bg,
                const float* __restrict__ gamma_, const float* __restrict__ beta_,
                const float* __restrict__ W1, const float* __restrict__ b1,
                const float* __restrict__ W2, const float* __restrict__ b2,
                float* __restrict__ out, int S) {
    extern __shared__ float smraw[];
    SmemLayout& sm = *reinterpret_cast<SmemLayout*>(smraw);
    const int tid  = threadIdx.x;
    const int lane = tid & 31;
    const int w    = tid >> 5;
    const int b    = blockIdx.x;
    const int nchunk = S / TCH;

    // ---- stage weights into smem (paired layouts) ----
    for (int i = tid; i < F * H; i += NTHR) {
        int j = i / H, k = i % H;
        sm.swp01[i] = make_float2(g_wX[0 * F * H + j * H + k], g_wX[1 * F * H + j * H + k]);
        sm.swp23[i] = make_float2(g_wX[2 * F * H + j * H + k], g_wX[3 * F * H + j * H + k]);
    }
    for (int i = tid; i < (H / 2) * H; i += NTHR) {
        int p = i / H, k = i % H;
        sm.swd2p[i] = make_float2(Wd[H * H + (2 * p) * H + k], Wd[H * H + (2 * p + 1) * H + k]);
    }
    for (int i = tid; i < 4 * H; i += NTHR) sm.sbias[i] = g_bias[i];
    for (int i = tid; i < 2 * H; i += NTHR) sm.sA[i] = g_A[i];
    for (int i = tid; i < H * H; i += NTHR) {
        sm.sWg2[i] = Wg[H * H + i];
        sm.sW1[i]  = W1[i];
    }
    for (int i = tid; i < H; i += NTHR) {
        sm.sbg2[i] = bg[H + i];
        sm.sb1[i]  = b1[i];
        sm.sW2[i]  = W2[i];
        sm.sgam[i] = gamma_[i];
        sm.sbet[i] = beta_[i];
    }
    if (tid == 0) sm.sb2 = b2[0];
    // seg2 read-buffer for chunk 0 = identity (B(0) reads seg2[1])
    if (tid < NWARP * H) sm.seg2[1][tid] = make_float2(1.f, 0.f);
    // stage xs[0] (chunk 0)
    if (tid < TCH * F / 4) {
        const float4* src = reinterpret_cast<const float4*>(x + (long)b * S * F);
        sm.xs[0][tid] = src[tid];
    }
    __syncthreads();

    // ---- persistent register weights (packed f32x2 pairs) ----
    ull wp01[F], wp23[F];
    #pragma unroll
    for (int j = 0; j < F; j++) {
        float2 p0 = sm.swp01[j * H + lane];
        float2 p2 = sm.swp23[j * H + lane];
        wp01[j] = pack2(p0.x, p0.y);
        wp23[j] = pack2(p2.x, p2.y);
    }
    ull wd2p[H / 2];
    #pragma unroll
    for (int p = 0; p < H / 2; p++) {
        float2 wv = sm.swd2p[p * H + lane];
        wd2p[p] = pack2(wv.x, wv.y);
    }
    const ull bias01 = pack2(sm.sbias[lane],         sm.sbias[H + lane]);
    const ull bias23 = pack2(sm.sbias[2 * H + lane], sm.sbias[3 * H + lane]);
    const float A1k = sm.sA[lane];
    const float A2k = sm.sA[H + lane];

    float carry1 = 0.f;   // replicated across all warps
    float s2     = 0.f;   // replicated block-2 final-state carry

    // ===== pipelined main loop: region r = A(chunk r) + B(chunk r-1) =====
    for (int r = 0; r <= nchunk; r++) {
        __syncthreads();
        const int rb = r & 1;

        // prefetch x chunk r+1 into xs[(r+1)&1] (read by A(r+1) next region)
        if (r + 1 < nchunk && tid < TCH * F / 4) {
            const float4* src = reinterpret_cast<const float4*>(x + ((long)b * S + (r + 1) * TCH) * F);
            sm.xs[rb ^ 1][tid] = src[tid];
        }

        // ---------- A(r): coefficients + block-1 segment transform ----------
        if (r < nchunk) {
            float Aw = 1.f, Xw = 0.f;
            #pragma unroll
            for (int i = 0; i < SEG; i++) {
                const int t = w * SEG + i;
                float4 xa  = sm.xs[rb][t * 2];
                float4 xb4 = sm.xs[rb][t * 2 + 1];
                float xv[8] = {xa.x, xa.y, xa.z, xa.w, xb4.x, xb4.y, xb4.z, xb4.w};
                ull a01 = bias01, a23 = bias23;
                #pragma unroll
                for (int j = 0; j < F; j++) {
                    ull sp = splat2(xv[j]);
                    fma2(a01, sp, wp01[j]);
                    fma2(a23, sp, wp23[j]);
                }
                float2 eu1 = unpack2(a01);   // {e, u1}
                float2 gu2 = unpack2(a23);   // {ug, u2}
                float d1, a1;
                splus_decay(eu1.y, A1k, d1, a1);
                float g1  = sigmoid_f(gu2.x);
                float xi1 = d1 * eu1.x;
                Xw = fmaf(a1, Xw, xi1);
                Aw *= a1;
                sm.cAXGE[rb][t * H + lane] = make_float4(a1, xi1, g1, eu1.x);
                sm.cU2[rb][t * H + lane]   = gu2.y;
            }
            sm.segAX[rb][w * H + lane] = make_float2(Aw, Xw);
        }

        // ---------- B(r-1): folds + scan + dot + block-2 transform ----------
        if (r >= 1) {
            const int cb = (r - 1) & 1;   // == rb ^ 1
            // fold block-1 prefix starts (redundant across warps)
            float st = 0.f;
            {
                float s = carry1;
                #pragma unroll
                for (int ww = 0; ww < NWARP; ww++) {
                    float2 ax = sm.segAX[cb][ww * H + lane];
                    if (ww == w) st = s;
                    s = fmaf(ax.x, s, ax.y);
                }
                carry1 = s;
            }
            // fold block-2 partials of chunk r-2
            {
                const float2* rd = sm.seg2[cb ^ 1];
                #pragma unroll
                for (int ww = 0; ww < NWARP; ww++) {
                    float2 ax = rd[ww * H + lane];
                    s2 = fmaf(ax.x, s2, ax.y);
                }
            }
            // P3a: apply block-1 scan, stash v rows
            float h1r[SEG];
            {
                float s1 = st;
                #pragma unroll
                for (int i = 0; i < SEG; i++) {
                    const int t = w * SEG + i;
                    float4 axge = sm.cAXGE[cb][t * H + lane];
                    s1 = fmaf(axge.x, s1, axge.y);
                    float v = s1 * axge.z;
                    h1r[i] = axge.w + v;
                    sm.cV[t * H + lane] = v;
                }
                if (r == nchunk && w == NWARP - 1) sm.hlast[lane] = h1r[SEG - 1];
            }
            __syncwarp();
            // P3b: dot v@Wd2 (paired LDS.128 + fma.f32x2), block-2 transform
            {
                float A2 = 1.f, X2 = 0.f;
                #pragma unroll
                for (int i = 0; i < SEG; i++) {
                    const int t = w * SEG + i;
                    const longlong2* vr = reinterpret_cast<const longlong2*>(sm.cV + t * H);
                    ull accA = 0ull, accB = 0ull;
                    #pragma unroll
                    for (int q = 0; q < 8; q++) {
                        longlong2 vq = vr[q];
                        fma2(accA, (ull)vq.x, wd2p[2 * q]);
                        fma2(accB, (ull)vq.y, wd2p[2 * q + 1]);
                    }
                    float2 fa = unpack2(accA), fb = unpack2(accB);
                    float u2 = sm.cU2[cb][t * H + lane] + ((fa.x + fa.y) + (fb.x + fb.y));
                    float d2, a2;
                    splus_decay(u2, A2k, d2, a2);
                    X2 = fmaf(a2, X2, d2 * h1r[i]);
                    A2 *= a2;
                }
                sm.seg2[cb][w * H + lane] = make_float2(A2, X2);
            }
        }
    }
    __syncthreads();

    // ---- epilogue (warp 0): fold last chunk's block-2 partials, gate2, LN, MLP ----
    if (w == 0) {
        const float2* fin = sm.seg2[(nchunk - 1) & 1];
        #pragma unroll
        for (int ww = 0; ww < NWARP; ww++) {
            float2 ax = fin[ww * H + lane];
            s2 = fmaf(ax.x, s2, ax.y);
        }
        float hl = sm.hlast[lane];
        float ug2 = sm.sbg2[lane];
        #pragma unroll
        for (int j = 0; j < H; j++)
            ug2 = fmaf(__shfl_sync(FULL, hl, j), sm.sWg2[j * H + lane], ug2);
        float g2 = sigmoid_f(ug2);
        float h2 = hl + s2 * g2;
        float mu = warp_allsum(h2) * (1.f / H);
        float d  = h2 - mu;
        float var = warp_allsum(d * d) * (1.f / H);
        float hn = d * rsqrtf(var + 1e-5f) * sm.sgam[lane] + sm.sbet[lane];
        float z1 = sm.sb1[lane];
        #pragma unroll
        for (int j = 0; j < H; j++)
            z1 = fmaf(__shfl_sync(FULL, hn, j), sm.sW1[j * H + lane], z1);
        float z = gelu_f(z1);
        float o = warp_allsum(z * sm.sW2[lane]);
        if (lane == 0) out[b] = o + sm.sb2;
    }
}

extern "C" void kernel_launch(void* const* d_in, const int* in_sizes, int n_in,
                              void* d_out, int out_size) {
    const float* x    = (const float*)d_in[0];
    const float* We   = (const float*)d_in[1];
    const float* be   = (const float*)d_in[2];
    const float* Wd   = (const float*)d_in[3];
    const float* bd   = (const float*)d_in[4];
    const float* Alog = (const float*)d_in[5];
    const float* Wg   = (const float*)d_in[6];
    const float* bg   = (const float*)d_in[7];
    const float* gam  = (const float*)d_in[8];
    const float* bet  = (const float*)d_in[9];
    const float* W1   = (const float*)d_in[10];
    const float* b1   = (const float*)d_in[11];
    const float* W2   = (const float*)d_in[12];
    const float* b2   = (const float*)d_in[13];
    float* out = (float*)d_out;

    int B = out_size;                  // 256
    int S = in_sizes[0] / (B * F);     // 4096

    setup_kernel<<<1, 256>>>(We, be, Wd, bd, Alog, Wg, bg);

    size_t smem = sizeof(SmemLayout);
    cudaFuncSetAttribute(forecast_kernel, cudaFuncAttributeMaxDynamicSharedMemorySize, (int)smem);
    forecast_kernel<<<B, NTHR, smem>>>(x, Wd, Wg, bg, gam, bet,
                                       W1, b1, W2, b2, out, S);
}

// round 7
// speedup vs baseline: 1.7324x; 1.7324x over previous
#include <cuda_runtime.h>
#include <math.h>

#define H 32
#define F 8
#define TCH 64
#define NWARP 8
#define SEG (TCH / NWARP)   // 8
#define NTHR (NWARP * 32)   // 256
#define FULL 0xffffffffu

typedef unsigned long long ull;

// Folded weights computed once per launch by setup_kernel.
__device__ float g_wX[4 * F * H];   // m=0 W_embed, m=1 We@Wd1, m=2 We@Wg1, m=3 We@Wd2
__device__ float g_bias[4 * H];
__device__ float g_A[2 * H];        // exp(A_log)

struct SmemLayout {
    float4 xs[2][TCH * F / 4];   // double-buffered x chunk (4KB)
    float4 cC[TCH * H];          // {a1, xi1, g1, e} per (t,k)  (32KB)
    float2 cU[TCH * H];          // {u2, h1} per (t,k)          (16KB)
    float  cV[TCH * H];          // v rows (8KB, 16B-aligned rows)
    float2 segAX[NWARP * H];     // block-1 segment transforms (this chunk)
    float2 seg2[2][NWARP * H];   // block-2 segment transforms (double-buffered)
    float  hlast[H];
    float2 swp01[F * H];         // paired weights {W0,W1}[j][lane]
    float2 swp23[F * H];         // paired weights {W2,W3}[j][lane]
    float2 swd2p[(H / 2) * H];   // paired Wd2 {row2p, row2p+1}[lane]
    float  sbias[4 * H];
    float  sA[2 * H];
    float  sWg2[H * H];
    float  sW1[H * H];
    float  sbg2[H];
    float  sb1[H];
    float  sW2[H];
    float  sgam[H];
    float  sbet[H];
    float  sb2;
};

__device__ __forceinline__ float ex2f(float x) { float r; asm("ex2.approx.f32 %0,%1;" : "=f"(r) : "f"(x)); return r; }
__device__ __forceinline__ float lg2f(float x) { float r; asm("lg2.approx.f32 %0,%1;" : "=f"(r) : "f"(x)); return r; }
__device__ __forceinline__ float tanh_f(float x) { float r; asm("tanh.approx.f32 %0,%1;" : "=f"(r) : "f"(x)); return r; }

__device__ __forceinline__ ull pack2(float lo, float hi) {
    ull r; asm("mov.b64 %0, {%1, %2};" : "=l"(r) : "r"(__float_as_uint(lo)), "r"(__float_as_uint(hi)));
    return r;
}
__device__ __forceinline__ ull splat2(float x) {
    ull r; asm("mov.b64 %0, {%1, %1};" : "=l"(r) : "r"(__float_as_uint(x)));
    return r;
}
__device__ __forceinline__ float2 unpack2(ull v) {
    unsigned lo, hi; asm("mov.b64 {%0, %1}, %2;" : "=r"(lo), "=r"(hi) : "l"(v));
    return make_float2(__uint_as_float(lo), __uint_as_float(hi));
}
__device__ __forceinline__ void fma2(ull& d, ull a, ull b) {
    asm("fma.rn.f32x2 %0, %1, %2, %0;" : "+l"(d) : "l"(a), "l"(b));
}

// d = softplus(u), a = exp(-A*d), computed in log2 domain: 3 MUFU total.
__device__ __forceinline__ void splus_decay(float u, float A, float& d, float& a) {
    const float L2E = 1.4426950408889634f;
    const float LN2 = 0.6931471805599453f;
    float p = ex2f(-fabsf(u) * L2E);
    float q = lg2f(1.f + p);
    float r = fmaf(fmaxf(u, 0.f), L2E, q);  // log2(1+e^u)
    d = r * LN2;
    a = ex2f(-A * r);
}

__device__ __forceinline__ float sigmoid_f(float u) {
    return fmaf(tanh_f(0.5f * u), 0.5f, 0.5f);
}

__device__ __forceinline__ float gelu_f(float u) {
    float inner = 0.7978845608028654f * fmaf(0.044715f * u, u * u, u);
    float ex = ex2f(2.f * inner * 1.4426950408889634f);
    float th = 1.f - __fdividef(2.f, ex + 1.f);
    return 0.5f * u * (1.f + th);
}

__device__ __forceinline__ float warp_allsum(float v) {
    #pragma unroll
    for (int off = 16; off; off >>= 1) v += __shfl_xor_sync(FULL, v, off);
    return v;
}

__global__ void setup_kernel(const float* __restrict__ We, const float* __restrict__ be,
                             const float* __restrict__ Wd, const float* __restrict__ bd,
                             const float* __restrict__ Alog, const float* __restrict__ Wg,
                             const float* __restrict__ bg) {
    int tid = threadIdx.x;
    for (int idx = tid; idx < F * H; idx += blockDim.x) g_wX[idx] = We[idx];
    for (int idx = tid; idx < 3 * F * H; idx += blockDim.x) {
        int m = idx / (F * H);
        int r = idx % (F * H);
        int f = r / H, k = r % H;
        const float* M = (m == 0) ? Wd : (m == 1) ? Wg : (Wd + H * H);
        float s = 0.f;
        for (int h = 0; h < H; h++) s += We[f * H + h] * M[h * H + k];
        g_wX[(m + 1) * F * H + r] = s;
    }
    for (int idx = tid; idx < 4 * H; idx += blockDim.x) {
        int m = idx / H, k = idx % H;
        float v;
        if (m == 0) v = be[k];
        else {
            const float* M; const float* bb;
            if (m == 1)      { M = Wd;         bb = bd;     }
            else if (m == 2) { M = Wg;         bb = bg;     }
            else             { M = Wd + H * H; bb = bd + H; }
            float s = 0.f;
            for (int h = 0; h < H; h++) s += be[h] * M[h * H + k];
            v = s + bb[k];
        }
        g_bias[idx] = v;
    }
    for (int idx = tid; idx < 2 * H; idx += blockDim.x) g_A[idx] = expf(Alog[idx]);
}

__global__ void __launch_bounds__(NTHR, 2)
forecast_kernel(const float* __restrict__ x,
                const float* __restrict__ Wd,
                const float* __restrict__ Wg, const float* __restrict__ bg,
                const float* __restrict__ gamma_, const float* __restrict__ beta_,
                const float* __restrict__ W1, const float* __restrict__ b1,
                const float* __restrict__ W2, const float* __restrict__ b2,
                float* __restrict__ out, int S) {
    extern __shared__ float smraw[];
    SmemLayout& sm = *reinterpret_cast<SmemLayout*>(smraw);
    const int tid  = threadIdx.x;
    const int lane = tid & 31;
    const int w    = tid >> 5;
    const int b    = blockIdx.x;
    const int nchunk = S / TCH;

    // ---- stage weights into smem (paired layouts) ----
    for (int i = tid; i < F * H; i += NTHR) {
        int j = i / H, k = i % H;
        sm.swp01[i] = make_float2(g_wX[0 * F * H + j * H + k], g_wX[1 * F * H + j * H + k]);
        sm.swp23[i] = make_float2(g_wX[2 * F * H + j * H + k], g_wX[3 * F * H + j * H + k]);
    }
    for (int i = tid; i < (H / 2) * H; i += NTHR) {
        int p = i / H, k = i % H;
        sm.swd2p[i] = make_float2(Wd[H * H + (2 * p) * H + k], Wd[H * H + (2 * p + 1) * H + k]);
    }
    for (int i = tid; i < 4 * H; i += NTHR) sm.sbias[i] = g_bias[i];
    for (int i = tid; i < 2 * H; i += NTHR) sm.sA[i] = g_A[i];
    for (int i = tid; i < H * H; i += NTHR) {
        sm.sWg2[i] = Wg[H * H + i];
        sm.sW1[i]  = W1[i];
    }
    for (int i = tid; i < H; i += NTHR) {
        sm.sbg2[i] = bg[H + i];
        sm.sb1[i]  = b1[i];
        sm.sW2[i]  = W2[i];
        sm.sgam[i] = gamma_[i];
        sm.sbet[i] = beta_[i];
    }
    if (tid == 0) sm.sb2 = b2[0];
    // seg2 read-buffer for chunk 0 = identity
    sm.seg2[1][tid] = make_float2(1.f, 0.f);
    // stage xs[0]
    if (tid < TCH * F / 4) {
        const float4* src = reinterpret_cast<const float4*>(x + (long)b * S * F);
        sm.xs[0][tid] = src[tid];
    }
    __syncthreads();

    // ---- persistent register weights (packed f32x2 pairs) ----
    ull wp01[F], wp23[F];
    #pragma unroll
    for (int j = 0; j < F; j++) {
        float2 p0 = sm.swp01[j * H + lane];
        float2 p2 = sm.swp23[j * H + lane];
        wp01[j] = pack2(p0.x, p0.y);
        wp23[j] = pack2(p2.x, p2.y);
    }
    ull wd2p[H / 2];
    #pragma unroll
    for (int p = 0; p < H / 2; p++) {
        float2 wv = sm.swd2p[p * H + lane];
        wd2p[p] = pack2(wv.x, wv.y);
    }
    const ull bias01 = pack2(sm.sbias[lane],         sm.sbias[H + lane]);
    const ull bias23 = pack2(sm.sbias[2 * H + lane], sm.sbias[3 * H + lane]);
    const float A1k = sm.sA[lane];
    const float A2k = sm.sA[H + lane];

    float carry1 = 0.f;   // replicated across warps
    float s2     = 0.f;   // replicated across warps (block-2 final-state carry)

    for (int c = 0; c < nchunk; c++) {
        const int cb = c & 1;
        // ================= PHASE A: coefficients + block-1 segment transform ====
        {
            float Aw = 1.f, Xw = 0.f;
            #pragma unroll
            for (int i = 0; i < SEG; i++) {
                const int t = w * SEG + i;
                float4 xa  = sm.xs[cb][t * 2];
                float4 xb4 = sm.xs[cb][t * 2 + 1];
                float xv[8] = {xa.x, xa.y, xa.z, xa.w, xb4.x, xb4.y, xb4.z, xb4.w};
                ull a01 = bias01, a23 = bias23;
                #pragma unroll
                for (int j = 0; j < F; j++) {
                    ull sp = splat2(xv[j]);
                    fma2(a01, sp, wp01[j]);
                    fma2(a23, sp, wp23[j]);
                }
                float2 eu1 = unpack2(a01);   // {e, u1}
                float2 gu2 = unpack2(a23);   // {ug, u2}
                float d1, a1;
                splus_decay(eu1.y, A1k, d1, a1);
                float g1  = sigmoid_f(gu2.x);
                float xi1 = d1 * eu1.x;
                Xw = fmaf(a1, Xw, xi1);
                Aw *= a1;
                sm.cC[t * H + lane] = make_float4(a1, xi1, g1, eu1.x);
                sm.cU[t * H + lane].x = gu2.y;
            }
            sm.segAX[w * H + lane] = make_float2(Aw, Xw);
        }
        __syncthreads();

        // ================= PHASE B ==========================================
        // prefetch next x chunk
        if (c + 1 < nchunk && tid < TCH * F / 4) {
            const float4* src = reinterpret_cast<const float4*>(x + ((long)b * S + (c + 1) * TCH) * F);
            sm.xs[cb ^ 1][tid] = src[tid];
        }
        // redundant fold (all warps): block-1 prefix start + new carry
        float st = 0.f;
        {
            float s = carry1;
            #pragma unroll
            for (int ww = 0; ww < NWARP; ww++) {
                float2 ax = sm.segAX[ww * H + lane];
                if (ww == w) st = s;
                s = fmaf(ax.x, s, ax.y);
            }
            carry1 = s;
        }
        // redundant fold: block-2 partials of previous chunk
        {
            const float2* rd = sm.seg2[cb ^ 1];
            #pragma unroll
            for (int ww = 0; ww < NWARP; ww++) {
                float2 ax = rd[ww * H + lane];
                s2 = fmaf(ax.x, s2, ax.y);
            }
        }
        // P3a: apply block-1 scan, stash v rows and h1
        {
            float s1 = st;
            #pragma unroll
            for (int i = 0; i < SEG; i++) {
                const int t = w * SEG + i;
                float4 cc = sm.cC[t * H + lane];   // {a1, xi1, g1, e}
                s1 = fmaf(cc.x, s1, cc.y);
                float v  = s1 * cc.z;
                float h1 = cc.w + v;
                sm.cV[t * H + lane]   = v;
                sm.cU[t * H + lane].y = h1;
                if (c == nchunk - 1 && w == NWARP - 1 && i == SEG - 1)
                    sm.hlast[lane] = h1;
            }
        }
        __syncwarp();
        // P3b: dot v@Wd2 via paired LDS.128 + fma.f32x2, block-2 transform
        {
            float A2 = 1.f, X2 = 0.f;
            #pragma unroll
            for (int i = 0; i < SEG; i++) {
                const int t = w * SEG + i;
                const longlong2* vr = reinterpret_cast<const longlong2*>(sm.cV + t * H);
                ull accA = 0ull, accB = 0ull;
                #pragma unroll
                for (int q = 0; q < 8; q++) {
                    longlong2 vq = vr[q];
                    fma2(accA, (ull)vq.x, wd2p[2 * q]);
                    fma2(accB, (ull)vq.y, wd2p[2 * q + 1]);
                }
                float2 fa = unpack2(accA), fb = unpack2(accB);
                float2 uh = sm.cU[t * H + lane];   // {u2, h1}
                float u2 = uh.x + ((fa.x + fa.y) + (fb.x + fb.y));
                float d2, a2;
                splus_decay(u2, A2k, d2, a2);
                X2 = fmaf(a2, X2, d2 * uh.y);
                A2 *= a2;
            }
            sm.seg2[cb][w * H + lane] = make_float2(A2, X2);
        }
        __syncthreads();
    }

    // ---- epilogue (warp 0): fold last chunk's block-2 partials, gate2, LN, MLP ----
    if (w == 0) {
        const float2* fin = sm.seg2[(nchunk - 1) & 1];
        #pragma unroll
        for (int ww = 0; ww < NWARP; ww++) {
            float2 ax = fin[ww * H + lane];
            s2 = fmaf(ax.x, s2, ax.y);
        }
        float hl = sm.hlast[lane];
        float ug2 = sm.sbg2[lane];
        #pragma unroll
        for (int j = 0; j < H; j++)
            ug2 = fmaf(__shfl_sync(FULL, hl, j), sm.sWg2[j * H + lane], ug2);
        float g2 = sigmoid_f(ug2);
        float h2 = hl + s2 * g2;
        float mu = warp_allsum(h2) * (1.f / H);
        float d  = h2 - mu;
        float var = warp_allsum(d * d) * (1.f / H);
        float hn = d * rsqrtf(var + 1e-5f) * sm.sgam[lane] + sm.sbet[lane];
        float z1 = sm.sb1[lane];
        #pragma unroll
        for (int j = 0; j < H; j++)
            z1 = fmaf(__shfl_sync(FULL, hn, j), sm.sW1[j * H + lane], z1);
        float z = gelu_f(z1);
        float o = warp_allsum(z * sm.sW2[lane]);
        if (lane == 0) out[b] = o + sm.sb2;
    }
}

extern "C" void kernel_launch(void* const* d_in, const int* in_sizes, int n_in,
                              void* d_out, int out_size) {
    const float* x    = (const float*)d_in[0];
    const float* We   = (const float*)d_in[1];
    const float* be   = (const float*)d_in[2];
    const float* Wd   = (const float*)d_in[3];
    const float* bd   = (const float*)d_in[4];
    const float* Alog = (const float*)d_in[5];
    const float* Wg   = (const float*)d_in[6];
    const float* bg   = (const float*)d_in[7];
    const float* gam  = (const float*)d_in[8];
    const float* bet  = (const float*)d_in[9];
    const float* W1   = (const float*)d_in[10];
    const float* b1   = (const float*)d_in[11];
    const float* W2   = (const float*)d_in[12];
    const float* b2   = (const float*)d_in[13];
    float* out = (float*)d_out;

    int B = out_size;                  // 256
    int S = in_sizes[0] / (B * F);     // 4096

    setup_kernel<<<1, 256>>>(We, be, Wd, bd, Alog, Wg, bg);

    size_t smem = sizeof(SmemLayout);
    cudaFuncSetAttribute(forecast_kernel, cudaFuncAttributeMaxDynamicSharedMemorySize, (int)smem);
    forecast_kernel<<<B, NTHR, smem>>>(x, Wd, Wg, bg, gam, bet,
                                       W1, b1, W2, b2, out, S);
}

// round 8
// speedup vs baseline: 1.8440x; 1.0644x over previous
#include <cuda_runtime.h>
#include <math.h>

#define H 32
#define F 8
#define TCH 32
#define NWARP 8
#define NAW 4               // A-warps (0-3) and B-warps (4-7)
#define SEGT 8              // timesteps per warp per region (TCH / NAW)
#define NTHR (NWARP * 32)   // 256
#define FULL 0xffffffffu

typedef unsigned long long ull;

// Folded weights computed once per launch by setup_kernel.
__device__ float g_wX[4 * F * H];   // m=0 W_embed, m=1 We@Wd1, m=2 We@Wg1, m=3 We@Wd2
__device__ float g_bias[4 * H];
__device__ float g_A[2 * H];        // exp(A_log)

struct SmemLayout {
    float4 xs[2][TCH * F / 4];   // double-buffered x chunk (2KB)
    float4 cC[2][TCH * H];       // {a1, xi1, g1, e}  (32KB)
    float  cU2[2][TCH * H];      // u2 (8KB)
    float  cV[TCH * H];          // v rows (4KB, 16B-aligned rows)
    float2 segAX[2][NAW * H];    // block-1 segment transforms (2KB)
    float2 seg2[2][NAW * H];     // block-2 segment transforms (2KB)
    float  hlast[H];
    float2 swp01[F * H];         // paired weights {W0,W1}[j][lane]
    float2 swp23[F * H];         // paired weights {W2,W3}[j][lane]
    float2 swd2p[(H / 2) * H];   // paired Wd2 {row2p, row2p+1}[lane]
    float  sbias[4 * H];
    float  sA[2 * H];
    float  sWg2[H * H];
    float  sW1[H * H];
    float  sbg2[H];
    float  sb1[H];
    float  sW2[H];
    float  sgam[H];
    float  sbet[H];
    float  sb2;
};

__device__ __forceinline__ float ex2f(float x) { float r; asm("ex2.approx.f32 %0,%1;" : "=f"(r) : "f"(x)); return r; }
__device__ __forceinline__ float lg2f(float x) { float r; asm("lg2.approx.f32 %0,%1;" : "=f"(r) : "f"(x)); return r; }
__device__ __forceinline__ float tanh_f(float x) { float r; asm("tanh.approx.f32 %0,%1;" : "=f"(r) : "f"(x)); return r; }

__device__ __forceinline__ ull pack2(float lo, float hi) {
    ull r; asm("mov.b64 %0, {%1, %2};" : "=l"(r) : "r"(__float_as_uint(lo)), "r"(__float_as_uint(hi)));
    return r;
}
__device__ __forceinline__ ull splat2(float x) {
    ull r; asm("mov.b64 %0, {%1, %1};" : "=l"(r) : "r"(__float_as_uint(x)));
    return r;
}
__device__ __forceinline__ float2 unpack2(ull v) {
    unsigned lo, hi; asm("mov.b64 {%0, %1}, %2;" : "=r"(lo), "=r"(hi) : "l"(v));
    return make_float2(__uint_as_float(lo), __uint_as_float(hi));
}
__device__ __forceinline__ void fma2(ull& d, ull a, ull b) {
    asm("fma.rn.f32x2 %0, %1, %2, %0;" : "+l"(d) : "l"(a), "l"(b));
}

// d = softplus(u), a = exp(-A*d), computed in log2 domain: 3 MUFU total.
__device__ __forceinline__ void splus_decay(float u, float A, float& d, float& a) {
    const float L2E = 1.4426950408889634f;
    const float LN2 = 0.6931471805599453f;
    float p = ex2f(-fabsf(u) * L2E);
    float q = lg2f(1.f + p);
    float r = fmaf(fmaxf(u, 0.f), L2E, q);  // log2(1+e^u)
    d = r * LN2;
    a = ex2f(-A * r);
}

__device__ __forceinline__ float sigmoid_f(float u) {
    return fmaf(tanh_f(0.5f * u), 0.5f, 0.5f);
}

__device__ __forceinline__ float gelu_f(float u) {
    float inner = 0.7978845608028654f * fmaf(0.044715f * u, u * u, u);
    float ex = ex2f(2.f * inner * 1.4426950408889634f);
    float th = 1.f - __fdividef(2.f, ex + 1.f);
    return 0.5f * u * (1.f + th);
}

__device__ __forceinline__ float warp_allsum(float v) {
    #pragma unroll
    for (int off = 16; off; off >>= 1) v += __shfl_xor_sync(FULL, v, off);
    return v;
}

__global__ void setup_kernel(const float* __restrict__ We, const float* __restrict__ be,
                             const float* __restrict__ Wd, const float* __restrict__ bd,
                             const float* __restrict__ Alog, const float* __restrict__ Wg,
                             const float* __restrict__ bg) {
    int tid = threadIdx.x;
    for (int idx = tid; idx < F * H; idx += blockDim.x) g_wX[idx] = We[idx];
    for (int idx = tid; idx < 3 * F * H; idx += blockDim.x) {
        int m = idx / (F * H);
        int r = idx % (F * H);
        int f = r / H, k = r % H;
        const float* M = (m == 0) ? Wd : (m == 1) ? Wg : (Wd + H * H);
        float s = 0.f;
        for (int h = 0; h < H; h++) s += We[f * H + h] * M[h * H + k];
        g_wX[(m + 1) * F * H + r] = s;
    }
    for (int idx = tid; idx < 4 * H; idx += blockDim.x) {
        int m = idx / H, k = idx % H;
        float v;
        if (m == 0) v = be[k];
        else {
            const float* M; const float* bb;
            if (m == 1)      { M = Wd;         bb = bd;     }
            else if (m == 2) { M = Wg;         bb = bg;     }
            else             { M = Wd + H * H; bb = bd + H; }
            float s = 0.f;
            for (int h = 0; h < H; h++) s += be[h] * M[h * H + k];
            v = s + bb[k];
        }
        g_bias[idx] = v;
    }
    for (int idx = tid; idx < 2 * H; idx += blockDim.x) g_A[idx] = expf(Alog[idx]);
}

__global__ void __launch_bounds__(NTHR, 2)
forecast_kernel(const float* __restrict__ x,
                const float* __restrict__ Wd,
                const float* __restrict__ Wg, const float* __restrict__ bg,
                const float* __restrict__ gamma_, const float* __restrict__ beta_,
                const float* __restrict__ W1, const float* __restrict__ b1,
                const float* __restrict__ W2, const float* __restrict__ b2,
                float* __restrict__ out, int S) {
    extern __shared__ float smraw[];
    SmemLayout& sm = *reinterpret_cast<SmemLayout*>(smraw);
    const int tid  = threadIdx.x;
    const int lane = tid & 31;
    const int w    = tid >> 5;
    const int b    = blockIdx.x;
    const int nchunk = S / TCH;

    // ---- stage weights into smem (paired layouts) ----
    for (int i = tid; i < F * H; i += NTHR) {
        int j = i / H, k = i % H;
        sm.swp01[i] = make_float2(g_wX[0 * F * H + j * H + k], g_wX[1 * F * H + j * H + k]);
        sm.swp23[i] = make_float2(g_wX[2 * F * H + j * H + k], g_wX[3 * F * H + j * H + k]);
    }
    for (int i = tid; i < (H / 2) * H; i += NTHR) {
        int p = i / H, k = i % H;
        sm.swd2p[i] = make_float2(Wd[H * H + (2 * p) * H + k], Wd[H * H + (2 * p + 1) * H + k]);
    }
    for (int i = tid; i < 4 * H; i += NTHR) sm.sbias[i] = g_bias[i];
    for (int i = tid; i < 2 * H; i += NTHR) sm.sA[i] = g_A[i];
    for (int i = tid; i < H * H; i += NTHR) {
        sm.sWg2[i] = Wg[H * H + i];
        sm.sW1[i]  = W1[i];
    }
    for (int i = tid; i < H; i += NTHR) {
        sm.sbg2[i] = bg[H + i];
        sm.sb1[i]  = b1[i];
        sm.sW2[i]  = W2[i];
        sm.sgam[i] = gamma_[i];
        sm.sbet[i] = beta_[i];
    }
    if (tid == 0) sm.sb2 = b2[0];
    // seg2 read-buffer for chunk 0 = identity (B(1) folds seg2[1])
    if (tid < NAW * H) sm.seg2[1][tid] = make_float2(1.f, 0.f);
    // stage xs[0]
    if (tid < TCH * F / 4) {
        const float4* src = reinterpret_cast<const float4*>(x + (long)b * S * F);
        sm.xs[0][tid] = src[tid];
    }
    __syncthreads();

    if (w < NAW) {
        // ================= A-WARPS: coefficient producer ======================
        ull wp01[F], wp23[F];
        #pragma unroll
        for (int j = 0; j < F; j++) {
            float2 p0 = sm.swp01[j * H + lane];
            float2 p2 = sm.swp23[j * H + lane];
            wp01[j] = pack2(p0.x, p0.y);
            wp23[j] = pack2(p2.x, p2.y);
        }
        const ull bias01 = pack2(sm.sbias[lane],         sm.sbias[H + lane]);
        const ull bias23 = pack2(sm.sbias[2 * H + lane], sm.sbias[3 * H + lane]);
        const float A1k = sm.sA[lane];

        for (int r = 0; r <= nchunk; r++) {
            __syncthreads();
            // prefetch x for chunk r+1 (threads 0-63 = warps 0,1)
            if (r + 1 < nchunk && tid < TCH * F / 4) {
                const float4* src = reinterpret_cast<const float4*>(x + ((long)b * S + (r + 1) * TCH) * F);
                sm.xs[(r + 1) & 1][tid] = src[tid];
            }
            if (r < nchunk) {
                const int rb = r & 1;
                float Aw = 1.f, Xw = 0.f;
                #pragma unroll
                for (int i = 0; i < SEGT; i++) {
                    const int t = w * SEGT + i;
                    float4 xa  = sm.xs[rb][t * 2];
                    float4 xb4 = sm.xs[rb][t * 2 + 1];
                    float xv[8] = {xa.x, xa.y, xa.z, xa.w, xb4.x, xb4.y, xb4.z, xb4.w};
                    ull a01 = bias01, a23 = bias23;
                    #pragma unroll
                    for (int j = 0; j < F; j++) {
                        ull sp = splat2(xv[j]);
                        fma2(a01, sp, wp01[j]);
                        fma2(a23, sp, wp23[j]);
                    }
                    float2 eu1 = unpack2(a01);   // {e, u1}
                    float2 gu2 = unpack2(a23);   // {ug, u2}
                    float d1, a1;
                    splus_decay(eu1.y, A1k, d1, a1);
                    float g1  = sigmoid_f(gu2.x);
                    float xi1 = d1 * eu1.x;
                    Xw = fmaf(a1, Xw, xi1);
                    Aw *= a1;
                    sm.cC[rb][t * H + lane]  = make_float4(a1, xi1, g1, eu1.x);
                    sm.cU2[rb][t * H + lane] = gu2.y;
                }
                sm.segAX[rb][w * H + lane] = make_float2(Aw, Xw);
            }
        }
        __syncthreads();   // final barrier (matches B side)
    } else {
        // ================= B-WARPS: scan + dot consumer =======================
        const int wb = w - NAW;
        ull wd2p[H / 2];
        #pragma unroll
        for (int p = 0; p < H / 2; p++) {
            float2 wv = sm.swd2p[p * H + lane];
            wd2p[p] = pack2(wv.x, wv.y);
        }
        const float A2k = sm.sA[H + lane];
        float carry1 = 0.f;   // replicated across B-warps
        float s2     = 0.f;   // block-2 final-state carry (replicated)

        for (int r = 0; r <= nchunk; r++) {
            __syncthreads();
            if (r >= 1) {
                const int cb = (r - 1) & 1;
                // fold block-1 prefix starts
                float st = 0.f;
                {
                    float s = carry1;
                    #pragma unroll
                    for (int ww = 0; ww < NAW; ww++) {
                        float2 ax = sm.segAX[cb][ww * H + lane];
                        if (ww == wb) st = s;
                        s = fmaf(ax.x, s, ax.y);
                    }
                    carry1 = s;
                }
                // fold block-2 partials of chunk r-2
                {
                    const float2* rd = sm.seg2[cb ^ 1];
                    #pragma unroll
                    for (int ww = 0; ww < NAW; ww++) {
                        float2 ax = rd[ww * H + lane];
                        s2 = fmaf(ax.x, s2, ax.y);
                    }
                }
                // P3a: apply block-1 scan, stash v rows, keep h1 in registers
                float h1r[SEGT];
                {
                    float s1 = st;
                    #pragma unroll
                    for (int i = 0; i < SEGT; i++) {
                        const int t = wb * SEGT + i;
                        float4 cc = sm.cC[cb][t * H + lane];   // {a1, xi1, g1, e}
                        s1 = fmaf(cc.x, s1, cc.y);
                        float v = s1 * cc.z;
                        h1r[i] = cc.w + v;
                        sm.cV[t * H + lane] = v;
                    }
                }
                __syncwarp();
                // P3b: dot v@Wd2 (paired LDS.128 + fma.f32x2), block-2 transform
                {
                    float A2 = 1.f, X2 = 0.f;
                    #pragma unroll
                    for (int i = 0; i < SEGT; i++) {
                        const int t = wb * SEGT + i;
                        const longlong2* vr = reinterpret_cast<const longlong2*>(sm.cV + t * H);
                        ull accA = 0ull, accB = 0ull;
                        #pragma unroll
                        for (int q = 0; q < 8; q++) {
                            longlong2 vq = vr[q];
                            fma2(accA, (ull)vq.x, wd2p[2 * q]);
                            fma2(accB, (ull)vq.y, wd2p[2 * q + 1]);
                        }
                        float2 fa = unpack2(accA), fb = unpack2(accB);
                        float u2 = sm.cU2[cb][t * H + lane] + ((fa.x + fa.y) + (fb.x + fb.y));
                        float d2, a2;
                        splus_decay(u2, A2k, d2, a2);
                        X2 = fmaf(a2, X2, d2 * h1r[i]);
                        A2 *= a2;
                    }
                    sm.seg2[cb][wb * H + lane] = make_float2(A2, X2);
                }
                if (r == nchunk && wb == NAW - 1) sm.hlast[lane] = h1r[SEGT - 1];
            }
        }
        __syncthreads();   // ensure hlast + final seg2 visible

        // ---- epilogue on warp 4 (wb == 0): gate2, LN, GELU MLP ----
        if (wb == 0) {
            const float2* fin = sm.seg2[(nchunk - 1) & 1];
            #pragma unroll
            for (int ww = 0; ww < NAW; ww++) {
                float2 ax = fin[ww * H + lane];
                s2 = fmaf(ax.x, s2, ax.y);
            }
            float hl = sm.hlast[lane];
            float ug2 = sm.sbg2[lane];
            #pragma unroll
            for (int j = 0; j < H; j++)
                ug2 = fmaf(__shfl_sync(FULL, hl, j), sm.sWg2[j * H + lane], ug2);
            float g2 = sigmoid_f(ug2);
            float h2 = hl + s2 * g2;
            float mu = warp_allsum(h2) * (1.f / H);
            float d  = h2 - mu;
            float var = warp_allsum(d * d) * (1.f / H);
            float hn = d * rsqrtf(var + 1e-5f) * sm.sgam[lane] + sm.sbet[lane];
            float z1 = sm.sb1[lane];
            #pragma unroll
            for (int j = 0; j < H; j++)
                z1 = fmaf(__shfl_sync(FULL, hn, j), sm.sW1[j * H + lane], z1);
            float z = gelu_f(z1);
            float o = warp_allsum(z * sm.sW2[lane]);
            if (lane == 0) out[b] = o + sm.sb2;
        }
    }
}

extern "C" void kernel_launch(void* const* d_in, const int* in_sizes, int n_in,
                              void* d_out, int out_size) {
    const float* x    = (const float*)d_in[0];
    const float* We   = (const float*)d_in[1];
    const float* be   = (const float*)d_in[2];
    const float* Wd   = (const float*)d_in[3];
    const float* bd   = (const float*)d_in[4];
    const float* Alog = (const float*)d_in[5];
    const float* Wg   = (const float*)d_in[6];
    const float* bg   = (const float*)d_in[7];
    const float* gam  = (const float*)d_in[8];
    const float* bet  = (const float*)d_in[9];
    const float* W1   = (const float*)d_in[10];
    const float* b1   = (const float*)d_in[11];
    const float* W2   = (const float*)d_in[12];
    const float* b2   = (const float*)d_in[13];
    float* out = (float*)d_out;

    int B = out_size;                  // 256
    int S = in_sizes[0] / (B * F);     // 4096

    setup_kernel<<<1, 256>>>(We, be, Wd, bd, Alog, Wg, bg);

    size_t smem = sizeof(SmemLayout);
    cudaFuncSetAttribute(forecast_kernel, cudaFuncAttributeMaxDynamicSharedMemorySize, (int)smem);
    forecast_kernel<<<B, NTHR, smem>>>(x, Wd, Wg, bg, gam, bet,
                                       W1, b1, W2, b2, out, S);
}